// round 2
// baseline (speedup 1.0000x reference)
#include <cuda_runtime.h>
#include <math.h>

#define B_   128
#define T_   2048
#define O_   128
#define E_   512
#define L_   34
#define KTOT 768          // E + O + O  (x = [y_1 | c_1], plus sh_1 for W_hh)
#define NG   512          // 4*O gate outputs
#define SCH  8            // T chunks for attention split
#define TCH  (T_ / SCH)   // 256 t per chunk

// d_out layout (tuple flatten): out[128*34] | c[128*128] | sh[128*128] | sc[128*128]
#define OUT_OFF_OUT 0
#define OUT_OFF_C   (B_ * L_)                    // 4352
#define OUT_OFF_SH  (OUT_OFF_C + B_ * O_)        // 20736
#define OUT_OFF_SC  (OUT_OFF_SH + B_ * O_)       // 37120

// ---------------- device scratch (no runtime alloc allowed) ----------------
__device__ __align__(16) float g_X[B_ * KTOT];   // packed [y1|c1|sh1] rows
__device__ __align__(16) float g_W[NG * KTOT];   // packed [W_ih row | W_hh row]
__device__ __align__(16) float g_gates[B_ * NG];
__device__ float g_pm[B_ * SCH];
__device__ float g_pr[B_ * SCH];
__device__ __align__(16) float g_pacc[B_ * SCH * O_];

// ---------------- pack X and W ----------------
__global__ void pack_kernel(const float* __restrict__ y1, const float* __restrict__ c1,
                            const float* __restrict__ sh1,
                            const float* __restrict__ Wih, const float* __restrict__ Whh) {
    int i = blockIdx.x * blockDim.x + threadIdx.x;
    const int NX = B_ * KTOT;        // 98304
    const int NW = NG * KTOT;        // 393216
    if (i < NX) {
        int b = i / KTOT, k = i - b * KTOT;
        float v;
        if (k < E_)            v = y1[b * E_ + k];
        else if (k < E_ + O_)  v = c1[b * O_ + (k - E_)];
        else                   v = sh1[b * O_ + (k - E_ - O_)];
        g_X[i] = v;
    } else if (i < NX + NW) {
        int j = i - NX;
        int n = j / KTOT, k = j - n * KTOT;
        float v;
        if (k < E_ + O_) v = Wih[n * (E_ + O_) + k];
        else             v = Whh[n * O_ + (k - (E_ + O_))];
        g_W[j] = v;
    }
}

// ---------------- gates GEMM: C[128,512] = X[128,768] * W^T, + biases ----------------
// BM=BN=BK=32, 256 threads, 2x2 per thread. Grid (16, 4). W read exactly once chip-wide.
__global__ void gemm_gates(const float* __restrict__ bih, const float* __restrict__ bhh) {
    __shared__ float Xs[32][33];
    __shared__ float Ws[32][33];
    int tid = threadIdx.x;
    int n0 = blockIdx.x * 32, m0 = blockIdx.y * 32;
    int ty = tid >> 4, tx = tid & 15;
    float c00 = 0.f, c01 = 0.f, c10 = 0.f, c11 = 0.f;
    int lr = tid >> 3;            // 0..31
    int lc = (tid & 7) * 4;       // 0..28
    for (int k0 = 0; k0 < KTOT; k0 += 32) {
        float4 xv = *(const float4*)&g_X[(m0 + lr) * KTOT + k0 + lc];
        Xs[lr][lc] = xv.x; Xs[lr][lc + 1] = xv.y; Xs[lr][lc + 2] = xv.z; Xs[lr][lc + 3] = xv.w;
        float4 wv = *(const float4*)&g_W[(n0 + lr) * KTOT + k0 + lc];
        Ws[lr][lc] = wv.x; Ws[lr][lc + 1] = wv.y; Ws[lr][lc + 2] = wv.z; Ws[lr][lc + 3] = wv.w;
        __syncthreads();
#pragma unroll
        for (int kk = 0; kk < 32; kk++) {
            float a0 = Xs[2 * ty][kk], a1 = Xs[2 * ty + 1][kk];
            float b0 = Ws[2 * tx][kk], b1 = Ws[2 * tx + 1][kk];
            c00 += a0 * b0; c01 += a0 * b1; c10 += a1 * b0; c11 += a1 * b1;
        }
        __syncthreads();
    }
    int m = m0 + 2 * ty, n = n0 + 2 * tx;
    float bias0 = bih[n] + bhh[n];
    float bias1 = bih[n + 1] + bhh[n + 1];
    g_gates[m * NG + n]           = c00 + bias0;
    g_gates[m * NG + n + 1]       = c01 + bias1;
    g_gates[(m + 1) * NG + n]     = c10 + bias0;
    g_gates[(m + 1) * NG + n + 1] = c11 + bias1;
}

// ---------------- LSTM activations: sc, sh ----------------
__device__ __forceinline__ float sigf(float x) { return 1.f / (1.f + __expf(-x)); }

__global__ void act_kernel(const float* __restrict__ sc1, float* __restrict__ dout) {
    int i = blockIdx.x * blockDim.x + threadIdx.x;
    if (i >= B_ * O_) return;
    int b = i >> 7, o = i & 127;
    const float* g = &g_gates[b * NG];
    float ig = g[o], fg = g[O_ + o], gg = g[2 * O_ + o], og = g[3 * O_ + o];
    float sc = sigf(fg) * sc1[i] + sigf(ig) * tanhf(gg);
    float sh = sigf(og) * tanhf(sc);
    dout[OUT_OFF_SC + i] = sc;
    dout[OUT_OFF_SH + i] = sh;
}

// ---------------- attention partials: online masked softmax + weighted hv sum ----------------
// grid (SCH, B_), 256 threads (8 warps). Warp w handles 32 consecutive t's, 4 at a time.
__global__ void attn_partial(const float* __restrict__ hk, const float* __restrict__ hv,
                             const float* __restrict__ mask, const float* __restrict__ dout) {
    __shared__ float s_m[8], s_r[8];
    __shared__ float s_acc[8][O_];
    int b = blockIdx.y;
    int chunk = blockIdx.x;
    int tid = threadIdx.x;
    int warp = tid >> 5, lane = tid & 31;

    float4 q = ((const float4*)(dout + OUT_OFF_SC + b * O_))[lane];
    const float4* hk4 = (const float4*)(hk) + (size_t)b * T_ * (O_ / 4);
    const float4* hv4 = (const float4*)(hv) + (size_t)b * T_ * (O_ / 4);
    const float* mrow = mask + (size_t)b * T_;

    int t0 = chunk * TCH + warp * 32;
    float m = -INFINITY, r = 0.f;
    float4 acc = make_float4(0.f, 0.f, 0.f, 0.f);

#pragma unroll 2
    for (int i = 0; i < 32; i += 4) {
        int t = t0 + i;
        float4 mk = *(const float4*)(mrow + t);          // uniform (broadcast)
        if (mk.x + mk.y + mk.z + mk.w == 0.f) continue;  // fully masked group (prefix mask)
        int base = t * (O_ / 4);                         // FIXED: no double b offset
        float4 k0 = hk4[base + lane];
        float4 k1 = hk4[base + 32 + lane];
        float4 k2 = hk4[base + 64 + lane];
        float4 k3 = hk4[base + 96 + lane];
        float d0 = k0.x * q.x + k0.y * q.y + k0.z * q.z + k0.w * q.w;
        float d1 = k1.x * q.x + k1.y * q.y + k1.z * q.z + k1.w * q.w;
        float d2 = k2.x * q.x + k2.y * q.y + k2.z * q.z + k2.w * q.w;
        float d3 = k3.x * q.x + k3.y * q.y + k3.z * q.z + k3.w * q.w;
#pragma unroll
        for (int off = 16; off; off >>= 1) {
            d0 += __shfl_xor_sync(0xffffffffu, d0, off);
            d1 += __shfl_xor_sync(0xffffffffu, d1, off);
            d2 += __shfl_xor_sync(0xffffffffu, d2, off);
            d3 += __shfl_xor_sync(0xffffffffu, d3, off);
        }
        // exclude masked positions from the max (reference renormalizes over valid only)
        d0 = (mk.x != 0.f) ? d0 : -INFINITY;
        d1 = (mk.y != 0.f) ? d1 : -INFINITY;
        d2 = (mk.z != 0.f) ? d2 : -INFINITY;
        d3 = (mk.w != 0.f) ? d3 : -INFINITY;
        float g = fmaxf(fmaxf(d0, d1), fmaxf(d2, d3));   // finite: >=1 valid in group
        float nm = fmaxf(m, g);
        float e0 = __expf(d0 - nm);                      // exp(-inf)=0 for masked
        float e1 = __expf(d1 - nm);
        float e2 = __expf(d2 - nm);
        float e3 = __expf(d3 - nm);
        float scale = __expf(m - nm);                    // exp(-inf)=0 on first valid group
        float4 v0 = hv4[base + lane];
        float4 v1 = hv4[base + 32 + lane];
        float4 v2 = hv4[base + 64 + lane];
        float4 v3 = hv4[base + 96 + lane];
        acc.x = acc.x * scale + e0 * v0.x + e1 * v1.x + e2 * v2.x + e3 * v3.x;
        acc.y = acc.y * scale + e0 * v0.y + e1 * v1.y + e2 * v2.y + e3 * v3.y;
        acc.z = acc.z * scale + e0 * v0.z + e1 * v1.z + e2 * v2.z + e3 * v3.z;
        acc.w = acc.w * scale + e0 * v0.w + e1 * v1.w + e2 * v2.w + e3 * v3.w;
        r = r * scale + (e0 + e1 + e2 + e3);
        m = nm;
    }

    // per-warp result -> shared
    s_acc[warp][4 * lane + 0] = acc.x;
    s_acc[warp][4 * lane + 1] = acc.y;
    s_acc[warp][4 * lane + 2] = acc.z;
    s_acc[warp][4 * lane + 3] = acc.w;
    if (lane == 0) { s_m[warp] = m; s_r[warp] = r; }
    __syncthreads();

    // block combine (128 threads active, one per o)
    if (tid < O_) {
        float M = -INFINITY;
#pragma unroll
        for (int w = 0; w < 8; w++) if (s_r[w] > 0.f) M = fmaxf(M, s_m[w]);
        float R = 0.f, A = 0.f;
#pragma unroll
        for (int w = 0; w < 8; w++) {
            if (s_r[w] > 0.f) {
                float f = __expf(s_m[w] - M);
                R += s_r[w] * f;
                A += s_acc[w][tid] * f;
            }
        }
        int p = b * SCH + chunk;
        g_pacc[p * O_ + tid] = A;
        if (tid == 0) { g_pm[p] = M; g_pr[p] = R; }
    }
}

// ---------------- combine partials -> c ----------------
__global__ void attn_combine(float* __restrict__ dout) {
    int b = blockIdx.x;
    int o = threadIdx.x;   // 128
    __shared__ float sM, sZ;
    if (o == 0) {
        float M = -INFINITY;
        for (int s = 0; s < SCH; s++) if (g_pr[b * SCH + s] > 0.f) M = fmaxf(M, g_pm[b * SCH + s]);
        float Z = 0.f;
        for (int s = 0; s < SCH; s++)
            if (g_pr[b * SCH + s] > 0.f) Z += g_pr[b * SCH + s] * __expf(g_pm[b * SCH + s] - M);
        sM = M; sZ = Z;
    }
    __syncthreads();
    float A = 0.f;
#pragma unroll
    for (int s = 0; s < SCH; s++) {
        if (g_pr[b * SCH + s] > 0.f)
            A += g_pacc[(b * SCH + s) * O_ + o] * __expf(g_pm[b * SCH + s] - sM);
    }
    dout[OUT_OFF_C + b * O_ + o] = A / sZ;
}

// ---------------- final MLP + softmax ----------------
__global__ void mlp_kernel(const float* __restrict__ W1, const float* __restrict__ b1,
                           const float* __restrict__ W2, const float* __restrict__ b2,
                           const float* __restrict__ W3, const float* __restrict__ b3,
                           float* __restrict__ dout) {
    __shared__ float shs[O_], cs[O_], h[L_], z[L_];
    int b = blockIdx.x;
    int tid = threadIdx.x;   // 128
    shs[tid] = dout[OUT_OFF_SH + b * O_ + tid];
    cs[tid]  = dout[OUT_OFF_C + b * O_ + tid];
    __syncthreads();
    if (tid < L_) {
        float a = b1[tid] + b2[tid];
        const float* w1 = &W1[tid * O_];
        const float* w2 = &W2[tid * O_];
#pragma unroll 4
        for (int k = 0; k < O_; k++) a += shs[k] * w1[k] + cs[k] * w2[k];
        h[tid] = fmaxf(a, 0.f);
    }
    __syncthreads();
    if (tid < L_) {
        float a = b3[tid];
        const float* w3 = &W3[tid * L_];
#pragma unroll
        for (int j = 0; j < L_; j++) a += h[j] * w3[j];
        z[tid] = a;
    }
    __syncthreads();
    if (tid == 0) {
        float M = -INFINITY;
        for (int j = 0; j < L_; j++) M = fmaxf(M, z[j]);
        float S = 0.f;
        for (int j = 0; j < L_; j++) { float e = __expf(z[j] - M); z[j] = e; S += e; }
        float inv = 1.f / S;
        for (int j = 0; j < L_; j++) dout[b * L_ + j] = z[j] * inv;
    }
}

// ---------------- launcher ----------------
extern "C" void kernel_launch(void* const* d_in, const int* in_sizes, int n_in,
                              void* d_out, int out_size) {
    // Canonical pointers (setup_inputs dict order). Defensive: if sizes say the
    // harness ordered inputs alphabetically by key, remap.
    const float* P[17];
    if (n_in >= 17 && in_sizes[0] == B_ * T_ * O_) {
        for (int i = 0; i < 17; i++) P[i] = (const float*)d_in[i];
    } else {
        // alphabetical key order: W1,W2,W3,W_hh,W_ih,b1,b2,b3,b_hh,b_ih,c_1,hk,hv,mask,sc_1,sh_1,y_1
        P[0]  = (const float*)d_in[11];  // hk
        P[1]  = (const float*)d_in[12];  // hv
        P[2]  = (const float*)d_in[16];  // y_1
        P[3]  = (const float*)d_in[10];  // c_1
        P[4]  = (const float*)d_in[15];  // sh_1
        P[5]  = (const float*)d_in[14];  // sc_1
        P[6]  = (const float*)d_in[13];  // mask
        P[7]  = (const float*)d_in[4];   // W_ih
        P[8]  = (const float*)d_in[9];   // b_ih
        P[9]  = (const float*)d_in[3];   // W_hh
        P[10] = (const float*)d_in[8];   // b_hh
        P[11] = (const float*)d_in[0];   // W1
        P[12] = (const float*)d_in[5];   // b1
        P[13] = (const float*)d_in[1];   // W2
        P[14] = (const float*)d_in[6];   // b2
        P[15] = (const float*)d_in[2];   // W3
        P[16] = (const float*)d_in[7];   // b3
    }
    const float *hk = P[0], *hv = P[1], *y1 = P[2], *c1 = P[3], *sh1 = P[4], *sc1 = P[5];
    const float *mask = P[6], *Wih = P[7], *bih = P[8], *Whh = P[9], *bhh = P[10];
    const float *W1 = P[11], *b1 = P[12], *W2 = P[13], *b2 = P[14], *W3 = P[15], *b3 = P[16];
    float* dout = (float*)d_out;

    int packN = B_ * KTOT + NG * KTOT;
    pack_kernel<<<(packN + 255) / 256, 256>>>(y1, c1, sh1, Wih, Whh);
    gemm_gates<<<dim3(NG / 32, B_ / 32), 256>>>(bih, bhh);
    act_kernel<<<(B_ * O_ + 255) / 256, 256>>>(sc1, dout);
    attn_partial<<<dim3(SCH, B_), 256>>>(hk, hv, mask, dout);
    attn_combine<<<B_, O_>>>(dout);
    mlp_kernel<<<B_, O_>>>(W1, b1, W2, b2, W3, b3, dout);
}

// round 3
// speedup vs baseline: 1.1931x; 1.1931x over previous
#include <cuda_runtime.h>
#include <math.h>

#define B_   128
#define T_   2048
#define O_   128
#define E_   512
#define L_   34
#define KTOT 768          // 512 (y1) + 128 (c1) + 128 (sh1)
#define NG   512          // 4*O gate outputs
#define KSPL 4            // split-K factor (768/4 = 192 = 6 tiles of 32)
#define KPER (KTOT / KSPL)
#define SCH  8            // attention chunk-blocks per batch row
#define NWARP (SCH * 8)   // 64 warps total per batch row

// d_out layout (tuple flatten): out[128*34] | c[128*128] | sh[128*128] | sc[128*128]
#define OUT_OFF_C   (B_ * L_)
#define OUT_OFF_SH  (OUT_OFF_C + B_ * O_)
#define OUT_OFF_SC  (OUT_OFF_SH + B_ * O_)

// ---------------- device scratch ----------------
__device__ __align__(16) float g_part[KSPL][B_ * NG];
__device__ int   g_len[B_];
__device__ float g_pm[B_ * SCH];
__device__ float g_pr[B_ * SCH];
__device__ __align__(16) float g_pacc[B_ * SCH * O_];

// ---------------- lengths from prefix mask ----------------
__global__ void len_kernel(const float* __restrict__ mask) {
    __shared__ float s[8];
    int b = blockIdx.x, tid = threadIdx.x, lane = tid & 31, warp = tid >> 5;
    const float4* m4 = (const float4*)(mask + (size_t)b * T_);
    float acc = 0.f;
    for (int i = tid; i < T_ / 4; i += 256) {
        float4 v = m4[i];
        acc += v.x + v.y + v.z + v.w;
    }
#pragma unroll
    for (int off = 16; off; off >>= 1) acc += __shfl_xor_sync(0xffffffffu, acc, off);
    if (lane == 0) s[warp] = acc;
    __syncthreads();
    if (tid == 0) {
        float t = 0.f;
        for (int w = 0; w < 8; w++) t += s[w];
        g_len[b] = (int)(t + 0.5f);
    }
}

// ---------------- split-K gates GEMM, direct source loads ----------------
// grid (NG/32, B_/32, KSPL); 256 threads; 2x2 per thread.
__global__ void gemm_gates(const float* __restrict__ y1, const float* __restrict__ c1,
                           const float* __restrict__ sh1,
                           const float* __restrict__ Wih, const float* __restrict__ Whh) {
    __shared__ float Xs[32][33];
    __shared__ float Ws[32][33];
    int tid = threadIdx.x;
    int n0 = blockIdx.x * 32, m0 = blockIdx.y * 32, ks = blockIdx.z;
    int ty = tid >> 4, tx = tid & 15;
    float c00 = 0.f, c01 = 0.f, c10 = 0.f, c11 = 0.f;
    int lr = tid >> 3;            // 0..31
    int lc = (tid & 7) * 4;       // 0,4,..,28

    for (int kk = 0; kk < KPER; kk += 32) {
        int k0 = ks * KPER + kk;
        // X tile: segment selected per 32-tile (boundaries 512,640 are tile-aligned)
        const float* xsrc;
        if (k0 < E_)            xsrc = y1  + (size_t)(m0 + lr) * E_ + k0 + lc;
        else if (k0 < E_ + O_)  xsrc = c1  + (size_t)(m0 + lr) * O_ + (k0 - E_) + lc;
        else                    xsrc = sh1 + (size_t)(m0 + lr) * O_ + (k0 - E_ - O_) + lc;
        float4 xv = *(const float4*)xsrc;
        Xs[lr][lc] = xv.x; Xs[lr][lc + 1] = xv.y; Xs[lr][lc + 2] = xv.z; Xs[lr][lc + 3] = xv.w;
        // W tile
        const float* wsrc;
        if (k0 < E_ + O_) wsrc = Wih + (size_t)(n0 + lr) * (E_ + O_) + k0 + lc;
        else              wsrc = Whh + (size_t)(n0 + lr) * O_ + (k0 - E_ - O_) + lc;
        float4 wv = *(const float4*)wsrc;
        Ws[lr][lc] = wv.x; Ws[lr][lc + 1] = wv.y; Ws[lr][lc + 2] = wv.z; Ws[lr][lc + 3] = wv.w;
        __syncthreads();
#pragma unroll
        for (int k = 0; k < 32; k++) {
            float a0 = Xs[2 * ty][k], a1 = Xs[2 * ty + 1][k];
            float b0 = Ws[2 * tx][k], b1 = Ws[2 * tx + 1][k];
            c00 += a0 * b0; c01 += a0 * b1; c10 += a1 * b0; c11 += a1 * b1;
        }
        __syncthreads();
    }
    int m = m0 + 2 * ty, n = n0 + 2 * tx;
    float* P = g_part[ks];
    P[m * NG + n]           = c00;
    P[m * NG + n + 1]       = c01;
    P[(m + 1) * NG + n]     = c10;
    P[(m + 1) * NG + n + 1] = c11;
}

// ---------------- reduce split-K + LSTM activations ----------------
__device__ __forceinline__ float sigf(float x) { return 1.f / (1.f + __expf(-x)); }

__global__ void act_kernel(const float* __restrict__ sc1,
                           const float* __restrict__ bih, const float* __restrict__ bhh,
                           float* __restrict__ dout) {
    int i = blockIdx.x * blockDim.x + threadIdx.x;
    if (i >= B_ * O_) return;
    int b = i >> 7, o = i & 127;
    float g4[4];
#pragma unroll
    for (int gi = 0; gi < 4; gi++) {
        int n = gi * O_ + o;
        float v = bih[n] + bhh[n];
#pragma unroll
        for (int ks = 0; ks < KSPL; ks++) v += g_part[ks][b * NG + n];
        g4[gi] = v;
    }
    float sc = sigf(g4[1]) * sc1[i] + sigf(g4[0]) * tanhf(g4[2]);
    float sh = sigf(g4[3]) * tanhf(sc);
    dout[OUT_OFF_SC + i] = sc;
    dout[OUT_OFF_SH + i] = sh;
}

// ---------------- attention partials: balanced spans, online masked softmax ----------------
// grid (SCH, B_), 256 threads. Global warp W = chunk*8+warp owns t in [W*span, min((W+1)*span, len)).
__global__ void attn_partial(const float* __restrict__ hk, const float* __restrict__ hv,
                             const float* __restrict__ dout) {
    __shared__ float s_m[8], s_r[8];
    __shared__ float s_acc[8][O_];
    int b = blockIdx.y;
    int tid = threadIdx.x;
    int warp = tid >> 5, lane = tid & 31;
    int W = blockIdx.x * 8 + warp;            // 0..63

    float4 q = ((const float4*)(dout + OUT_OFF_SC + b * O_))[lane];
    const float4* hk4 = (const float4*)(hk) + (size_t)b * T_ * (O_ / 4);
    const float4* hv4 = (const float4*)(hv) + (size_t)b * T_ * (O_ / 4);

    int len = g_len[b];
    int span = (len + NWARP - 1) / NWARP;
    int start = W * span;
    int end = min(start + span, len);

    float m = -INFINITY, r = 0.f;
    float4 acc = make_float4(0.f, 0.f, 0.f, 0.f);

    for (int t = start; t < end; t += 4) {
        int t1 = min(t + 1, T_ - 1), t2 = min(t + 2, T_ - 1), t3 = min(t + 3, T_ - 1);
        int b0 = t * (O_ / 4), b1 = t1 * (O_ / 4), b2 = t2 * (O_ / 4), b3 = t3 * (O_ / 4);
        float4 k0 = hk4[b0 + lane];
        float4 k1 = hk4[b1 + lane];
        float4 k2 = hk4[b2 + lane];
        float4 k3 = hk4[b3 + lane];
        float d0 = k0.x * q.x + k0.y * q.y + k0.z * q.z + k0.w * q.w;
        float d1 = k1.x * q.x + k1.y * q.y + k1.z * q.z + k1.w * q.w;
        float d2 = k2.x * q.x + k2.y * q.y + k2.z * q.z + k2.w * q.w;
        float d3 = k3.x * q.x + k3.y * q.y + k3.z * q.z + k3.w * q.w;
#pragma unroll
        for (int off = 16; off; off >>= 1) {
            d0 += __shfl_xor_sync(0xffffffffu, d0, off);
            d1 += __shfl_xor_sync(0xffffffffu, d1, off);
            d2 += __shfl_xor_sync(0xffffffffu, d2, off);
            d3 += __shfl_xor_sync(0xffffffffu, d3, off);
        }
        // tail masking: only elements with t+j < end are valid
        d1 = (t + 1 < end) ? d1 : -INFINITY;
        d2 = (t + 2 < end) ? d2 : -INFINITY;
        d3 = (t + 3 < end) ? d3 : -INFINITY;
        float g = fmaxf(fmaxf(d0, d1), fmaxf(d2, d3));
        float nm = fmaxf(m, g);
        float e0 = __expf(d0 - nm);
        float e1 = __expf(d1 - nm);
        float e2 = __expf(d2 - nm);
        float e3 = __expf(d3 - nm);
        float scale = __expf(m - nm);
        float4 v0 = hv4[b0 + lane];
        float4 v1 = hv4[b1 + lane];
        float4 v2 = hv4[b2 + lane];
        float4 v3 = hv4[b3 + lane];
        acc.x = acc.x * scale + e0 * v0.x + e1 * v1.x + e2 * v2.x + e3 * v3.x;
        acc.y = acc.y * scale + e0 * v0.y + e1 * v1.y + e2 * v2.y + e3 * v3.y;
        acc.z = acc.z * scale + e0 * v0.z + e1 * v1.z + e2 * v2.z + e3 * v3.z;
        acc.w = acc.w * scale + e0 * v0.w + e1 * v1.w + e2 * v2.w + e3 * v3.w;
        r = r * scale + (e0 + e1 + e2 + e3);
        m = nm;
    }

    s_acc[warp][4 * lane + 0] = acc.x;
    s_acc[warp][4 * lane + 1] = acc.y;
    s_acc[warp][4 * lane + 2] = acc.z;
    s_acc[warp][4 * lane + 3] = acc.w;
    if (lane == 0) { s_m[warp] = m; s_r[warp] = r; }
    __syncthreads();

    if (tid < O_) {
        float M = -INFINITY;
#pragma unroll
        for (int w = 0; w < 8; w++) if (s_r[w] > 0.f) M = fmaxf(M, s_m[w]);
        float R = 0.f, A = 0.f;
#pragma unroll
        for (int w = 0; w < 8; w++) {
            if (s_r[w] > 0.f) {
                float f = __expf(s_m[w] - M);
                R += s_r[w] * f;
                A += s_acc[w][tid] * f;
            }
        }
        int p = b * SCH + blockIdx.x;
        g_pacc[p * O_ + tid] = A;
        if (tid == 0) { g_pm[p] = M; g_pr[p] = R; }
    }
}

// ---------------- fused: combine partials -> c, then MLP + softmax ----------------
__global__ void final_kernel(const float* __restrict__ W1, const float* __restrict__ b1,
                             const float* __restrict__ W2, const float* __restrict__ b2,
                             const float* __restrict__ W3, const float* __restrict__ b3,
                             float* __restrict__ dout) {
    __shared__ float shs[O_], cs[O_], h[L_], z[L_];
    __shared__ float sM, sZ;
    int b = blockIdx.x;
    int tid = threadIdx.x;   // 128

    if (tid == 0) {
        float M = -INFINITY;
        for (int s = 0; s < SCH; s++) if (g_pr[b * SCH + s] > 0.f) M = fmaxf(M, g_pm[b * SCH + s]);
        float Z = 0.f;
        for (int s = 0; s < SCH; s++)
            if (g_pr[b * SCH + s] > 0.f) Z += g_pr[b * SCH + s] * __expf(g_pm[b * SCH + s] - M);
        sM = M; sZ = Z;
    }
    shs[tid] = dout[OUT_OFF_SH + b * O_ + tid];
    __syncthreads();
    float A = 0.f;
#pragma unroll
    for (int s = 0; s < SCH; s++) {
        if (g_pr[b * SCH + s] > 0.f)
            A += g_pacc[(b * SCH + s) * O_ + tid] * __expf(g_pm[b * SCH + s] - sM);
    }
    float cval = A / sZ;
    cs[tid] = cval;
    dout[OUT_OFF_C + b * O_ + tid] = cval;
    __syncthreads();

    if (tid < L_) {
        float a = b1[tid] + b2[tid];
        const float* w1 = &W1[tid * O_];
        const float* w2 = &W2[tid * O_];
#pragma unroll 4
        for (int k = 0; k < O_; k++) a += shs[k] * w1[k] + cs[k] * w2[k];
        h[tid] = fmaxf(a, 0.f);
    }
    __syncthreads();
    if (tid < L_) {
        float a = b3[tid];
        const float* w3 = &W3[tid * L_];
#pragma unroll
        for (int j = 0; j < L_; j++) a += h[j] * w3[j];
        z[tid] = a;
    }
    __syncthreads();
    if (tid == 0) {
        float M = -INFINITY;
        for (int j = 0; j < L_; j++) M = fmaxf(M, z[j]);
        float S = 0.f;
        for (int j = 0; j < L_; j++) { float e = __expf(z[j] - M); z[j] = e; S += e; }
        float inv = 1.f / S;
        for (int j = 0; j < L_; j++) dout[b * L_ + j] = z[j] * inv;
    }
}

// ---------------- launcher ----------------
extern "C" void kernel_launch(void* const* d_in, const int* in_sizes, int n_in,
                              void* d_out, int out_size) {
    const float* P[17];
    if (n_in >= 17 && in_sizes[0] == B_ * T_ * O_) {
        for (int i = 0; i < 17; i++) P[i] = (const float*)d_in[i];
    } else {
        // alphabetical key order fallback
        P[0]  = (const float*)d_in[11];  // hk
        P[1]  = (const float*)d_in[12];  // hv
        P[2]  = (const float*)d_in[16];  // y_1
        P[3]  = (const float*)d_in[10];  // c_1
        P[4]  = (const float*)d_in[15];  // sh_1
        P[5]  = (const float*)d_in[14];  // sc_1
        P[6]  = (const float*)d_in[13];  // mask
        P[7]  = (const float*)d_in[4];   // W_ih
        P[8]  = (const float*)d_in[9];   // b_ih
        P[9]  = (const float*)d_in[3];   // W_hh
        P[10] = (const float*)d_in[8];   // b_hh
        P[11] = (const float*)d_in[0];   // W1
        P[12] = (const float*)d_in[5];   // b1
        P[13] = (const float*)d_in[1];   // W2
        P[14] = (const float*)d_in[6];   // b2
        P[15] = (const float*)d_in[2];   // W3
        P[16] = (const float*)d_in[7];   // b3
    }
    const float *hk = P[0], *hv = P[1], *y1 = P[2], *c1 = P[3], *sh1 = P[4], *sc1 = P[5];
    const float *mask = P[6], *Wih = P[7], *bih = P[8], *Whh = P[9], *bhh = P[10];
    const float *W1 = P[11], *b1 = P[12], *W2 = P[13], *b2 = P[14], *W3 = P[15], *b3 = P[16];
    float* dout = (float*)d_out;

    len_kernel<<<B_, 256>>>(mask);
    gemm_gates<<<dim3(NG / 32, B_ / 32, KSPL), 256>>>(y1, c1, sh1, Wih, Whh);
    act_kernel<<<(B_ * O_ + 255) / 256, 256>>>(sc1, bih, bhh, dout);
    attn_partial<<<dim3(SCH, B_), 256>>>(hk, hv, dout);
    final_kernel<<<B_, O_>>>(W1, b1, W2, b2, W3, b3, dout);
}